// round 6
// baseline (speedup 1.0000x reference)
#include <cuda_runtime.h>
#include <math.h>
#include <float.h>

// Temporal Contrast Enhancement as three cascaded max/min-affine parallel
// scans, v4: 512 threads x 16 samples (CHUNK=8192), running-squared
// implicit-A (bA = q; bA *= bA each KS step; after warp steps bA = q^32 =
// cross-warp seed; after cross-warp steps bA = q^512*... = block factor),
// so zero power-table registers. Two-scalar phase-1 + carry-seeded fixup,
// 1 barrier per scan, 3-buffer smem rotation.
//
//   envd:  y[t] = max(x[t], (1-a)*x[t] + a*y[t-1])
//   enva:  y[t] = min(x[t], (1-a)*x[t] + a*y[t-1])
// y -> op(U, A*y + V), A>0 composes associatively. Exact.

#define THREADS 512
#define RPT 16
#define CHUNK (THREADS * RPT)    // 8192
#define NWARPS (THREADS / 32)    // 16
#define T_LEN 88200

template <bool MAXOP>
__device__ __forceinline__ float sel(float a, float b) {
    return MAXOP ? fmaxf(a, b) : fminf(a, b);
}

// Block scan of one chunk. in[RPT] -> out[RPT] (distinct register arrays).
// q = alpha^RPT. qlane = q^lane (per-lane). qwid = (q^32)^wid (per-warp).
// carry: replicated resolved value entering this chunk. All threads hold
// full RPT samples (tail chunk zero-padded) -> every aggregate's decay is
// position-deterministic, carried implicitly by the running factor bA.
template <bool MAXOP>
__device__ __forceinline__ void scan16(const float* in, float* out,
                                       float alpha, float om, float q,
                                       float qlane, float qwid,
                                       float& carry, float2* sw,
                                       int lane, int wid)
{
    // Phase 1: per-thread running linear response v and local envelope yl.
    float v = om * in[0];
    float yl = in[0];
    out[0] = yl;
    #pragma unroll
    for (int j = 1; j < RPT; j++) {
        float omm = om * in[j];
        v  = fmaf(alpha, v, omm);
        yl = sel<MAXOP>(in[j], fmaf(alpha, yl, omm));
        out[j] = yl;
    }

    // Warp Kogge-Stone over thread aggregates (U, V).
    // Step k factor = q^(2^k): running bA, squared after each step.
    float U = yl, V = v;
    float bA = q;
    #pragma unroll
    for (int k = 0; k < 5; k++) {
        const int d = 1 << k;
        float uU = __shfl_up_sync(0xffffffffu, U, d);
        float uV = __shfl_up_sync(0xffffffffu, V, d);
        if (lane >= d) {
            U = sel<MAXOP>(U, fmaf(bA, uU, V));
            V = fmaf(bA, uV, V);
        }
        bA *= bA;                 // after loop: bA = q^32
    }
    // Thread-exclusive (within warp): value at lane-1; A = q^lane implicit.
    float Ue = __shfl_up_sync(0xffffffffu, U, 1);
    float Ve = __shfl_up_sync(0xffffffffu, V, 1);

    if (lane == 31) sw[wid] = make_float2(U, V);
    __syncthreads();

    // Cross-warp scan over NWARPS aggregates, redundant in every warp.
    // Step k factor = (q^32)^(2^k): continue squaring the same bA.
    float cU = MAXOP ? -FLT_MAX : FLT_MAX, cV = 0.0f;
    if (lane < NWARPS) { float2 t = sw[lane]; cU = t.x; cV = t.y; }
    #pragma unroll
    for (int k = 0; k < 4; k++) {            // NWARPS = 16 -> 4 steps
        const int d = 1 << k;
        float uU = __shfl_up_sync(0xffffffffu, cU, d);
        float uV = __shfl_up_sync(0xffffffffu, cV, d);
        if (lane >= d) {
            cU = sel<MAXOP>(cU, fmaf(bA, uU, cV));
            cV = fmaf(bA, uV, cV);
        }
        bA *= bA;                 // after loop: bA = q^512 = block factor
    }

    // Warp-incoming resolved value: apply exclusive-over-warps to carry.
    const int src = (wid == 0) ? 0 : (wid - 1);
    float WU = __shfl_sync(0xffffffffu, cU, src);
    float WV = __shfl_sync(0xffffffffu, cV, src);
    float c_w = (wid == 0) ? carry : sel<MAXOP>(WU, fmaf(qwid, carry, WV));

    // Block total (lane NWARPS-1) for the carry update; factor = bA.
    float TU = __shfl_sync(0xffffffffu, cU, NWARPS - 1);
    float TV = __shfl_sync(0xffffffffu, cV, NWARPS - 1);
    float ncar = sel<MAXOP>(TU, fmaf(bA, carry, TV));

    // Thread-incoming resolved value.
    float c = (lane == 0) ? c_w : sel<MAXOP>(Ue, fmaf(qlane, c_w, Ve));

    // Fixup: linear recurrence seeded with c; out = op(local, z).
    float z = c;
    #pragma unroll
    for (int j = 0; j < RPT; j++) {
        z = fmaf(alpha, z, om * in[j]);
        out[j] = sel<MAXOP>(out[j], z);
    }
    carry = ncar;
}

__global__ void __launch_bounds__(THREADS, 2)
tce_kernel(const float* __restrict__ x,
           const float* __restrict__ p_tauA,
           const float* __restrict__ p_tauD,
           const float* __restrict__ p_nu,
           const float* __restrict__ p_dbr,
           float* __restrict__ out, int T)
{
    __shared__ float2 swb[3][NWARPS];

    const int lane = threadIdx.x & 31;
    const int wid  = threadIdx.x >> 5;
    const long long ch = blockIdx.x;
    const float* xc = x + ch * (long long)T;
    float* oc = out + ch * (long long)T;

    // Scalar params (replicate reference clip chain)
    float tauA = fminf(fmaxf(p_tauA[0], 1.0f), 100.0f);
    tauA = fminf(fmaxf(tauA, 0.1f), 1000.0f) * 0.001f;
    const float aa = expf(-1.0f / (tauA * 44100.0f));
    float tauD = fminf(fmaxf(p_tauD[0], 1.0f), 100.0f);
    tauD = fminf(fmaxf(tauD, 0.1f), 1000.0f) * 0.001f;
    const float ad = expf(-1.0f / (tauD * 44100.0f));
    const float nuAmp = exp10f(fminf(fmaxf(p_nu[0], -60.0f), 0.0f) * 0.05f);
    const float reg   = exp10f(fminf(fmaxf(p_dbr[0], -120.0f), -60.0f) * 0.05f);
    const float omd = 1.0f - ad;
    const float oma = 1.0f - aa;

    // q = alpha^16 (4 squarings). Per-lane q^lane; per-warp (q^32)^wid.
    float qd = ad * ad; qd *= qd; qd *= qd; qd *= qd;   // ad^16
    float qa = aa * aa; qa *= qa; qa *= qa; qa *= qa;   // aa^16
    float qdlane = 1.0f, qalane = 1.0f;
    for (int i = 0; i < lane; i++) { qdlane *= qd; qalane *= qa; }
    float qwd32 = qd * qd; qwd32 *= qwd32; qwd32 *= qwd32;
    qwd32 *= qwd32; qwd32 *= qwd32;                     // qd^32
    float qwa32 = qa * qa; qwa32 *= qwa32; qwa32 *= qwa32;
    qwa32 *= qwa32; qwa32 *= qwa32;                     // qa^32
    float qwidd = 1.0f, qwida = 1.0f;
    for (int i = 0; i < wid; i++) { qwidd *= qwd32; qwida *= qwa32; }

    float cd = 0.0f, ca = 0.0f, ce = 0.0f;   // carries

    for (int base = 0; base < T; base += CHUNK) {
        const int off = base + (int)threadIdx.x * RPT;
        float A_[RPT], B_[RPT];

        // Load |x| (zero-padded beyond T; tail chunk only)
        #pragma unroll
        for (int g = 0; g < RPT / 4; g++) {
            const int o = off + g * 4;
            float4 v = make_float4(0.f, 0.f, 0.f, 0.f);
            if (o + 4 <= T) {
                v = *reinterpret_cast<const float4*>(xc + o);
            } else if (o < T) {
                v.x = xc[o];
                if (o + 1 < T) v.y = xc[o + 1];
                if (o + 2 < T) v.z = xc[o + 2];
            }
            A_[4 * g + 0] = fabsf(v.x);
            A_[4 * g + 1] = fabsf(v.y);
            A_[4 * g + 2] = fabsf(v.z);
            A_[4 * g + 3] = fabsf(v.w);
        }

        // et_d = envd(|x|)   (max, alpha_d):  A_ -> B_
        scan16<true >(A_, B_, ad, omd, qd, qdlane, qwidd, cd, swb[0], lane, wid);
        // et_a = enva(et_d)  (min, alpha_a):  B_ -> A_
        scan16<false>(B_, A_, aa, oma, qa, qalane, qwida, ca, swb[1], lane, wid);
        // et = relu(et_d - et_a - nuAmp)   -> A_
        #pragma unroll
        for (int j = 0; j < RPT; j++)
            A_[j] = fmaxf(B_[j] - A_[j] - nuAmp, 0.0f);
        // et_env = envd(et)  (max, alpha_d):  A_ -> B_
        scan16<true >(A_, B_, ad, omd, qd, qdlane, qwidd, ce, swb[2], lane, wid);

        // out = x * et / (et_env + reg)   (x reloaded; L1/L2-hot)
        #pragma unroll
        for (int g = 0; g < RPT / 4; g++) {
            const int o = off + g * 4;
            if (o + 4 <= T) {
                float4 xv = *reinterpret_cast<const float4*>(xc + o);
                float4 r;
                r.x = xv.x * __fdividef(A_[4 * g + 0], B_[4 * g + 0] + reg);
                r.y = xv.y * __fdividef(A_[4 * g + 1], B_[4 * g + 1] + reg);
                r.z = xv.z * __fdividef(A_[4 * g + 2], B_[4 * g + 2] + reg);
                r.w = xv.w * __fdividef(A_[4 * g + 3], B_[4 * g + 3] + reg);
                *reinterpret_cast<float4*>(oc + o) = r;
            } else if (o < T) {
                oc[o] = xc[o] * __fdividef(A_[4 * g + 0], B_[4 * g + 0] + reg);
                if (o + 1 < T)
                    oc[o + 1] = xc[o + 1] * __fdividef(A_[4 * g + 1], B_[4 * g + 1] + reg);
                if (o + 2 < T)
                    oc[o + 2] = xc[o + 2] * __fdividef(A_[4 * g + 2], B_[4 * g + 2] + reg);
            }
        }
    }
}

extern "C" void kernel_launch(void* const* d_in, const int* in_sizes, int n_in,
                              void* d_out, int out_size)
{
    const float* x      = (const float*)d_in[0];
    const float* tauAtc = (const float*)d_in[1];
    const float* tauDtc = (const float*)d_in[2];
    const float* nu     = (const float*)d_in[3];
    const float* dbr    = (const float*)d_in[4];
    float* out = (float*)d_out;

    const int T = T_LEN;
    const int channels = in_sizes[0] / T;   // 256

    tce_kernel<<<channels, THREADS>>>(x, tauAtc, tauDtc, nu, dbr, out, T);
}

// round 14
// speedup vs baseline: 1.0793x; 1.0793x over previous
#include <cuda_runtime.h>
#include <math.h>
#include <float.h>

// Temporal Contrast Enhancement as three cascaded max/min-affine parallel
// scans, v5: 384 threads x 16 samples (CHUNK=6144). RPT=16 amortizes the
// scan machinery; THREADS=384 with launch_bounds(384,2) gives an 85-reg
// budget so the 32 array registers fit WITHOUT spilling (v4's 512x16
// spilled at the 64-reg cap and regressed). Running-squared implicit-A;
// block carry factor qblk = (q^32)^12 precomputed (running bA would give
// (q^32)^16 after 4 KS steps over 12 warps).
//
//   envd:  y[t] = max(x[t], (1-a)*x[t] + a*y[t-1])
//   enva:  y[t] = min(x[t], (1-a)*x[t] + a*y[t-1])
// y -> op(U, A*y + V), A>0 composes associatively. Exact.

#define THREADS 384
#define RPT 16
#define CHUNK (THREADS * RPT)    // 6144
#define NWARPS (THREADS / 32)    // 12
#define T_LEN 88200

template <bool MAXOP>
__device__ __forceinline__ float sel(float a, float b) {
    return MAXOP ? fmaxf(a, b) : fminf(a, b);
}

// Block scan of one chunk. in[RPT] -> out[RPT] (distinct register arrays).
// q = alpha^RPT. qlane = q^lane. qwid = (q^32)^wid. qblk = (q^32)^NWARPS.
// carry: replicated resolved value entering this chunk. Tail chunk is
// zero-padded so every aggregate's decay is position-deterministic.
template <bool MAXOP>
__device__ __forceinline__ void scan16(const float* in, float* out,
                                       float alpha, float om, float q,
                                       float qlane, float qwid, float qblk,
                                       float& carry, float2* sw,
                                       int lane, int wid)
{
    // Phase 1: per-thread running linear response v and local envelope yl.
    float v = om * in[0];
    float yl = in[0];
    out[0] = yl;
    #pragma unroll
    for (int j = 1; j < RPT; j++) {
        float omm = om * in[j];
        v  = fmaf(alpha, v, omm);
        yl = sel<MAXOP>(in[j], fmaf(alpha, yl, omm));
        out[j] = yl;
    }

    // Warp Kogge-Stone over thread aggregates (U, V).
    // Step k factor = q^(2^k): running bA, squared after each step.
    float U = yl, V = v;
    float bA = q;
    #pragma unroll
    for (int k = 0; k < 5; k++) {
        const int d = 1 << k;
        float uU = __shfl_up_sync(0xffffffffu, U, d);
        float uV = __shfl_up_sync(0xffffffffu, V, d);
        if (lane >= d) {
            U = sel<MAXOP>(U, fmaf(bA, uU, V));
            V = fmaf(bA, uV, V);
        }
        bA *= bA;                 // after loop: bA = q^32 (warp factor)
    }
    // Thread-exclusive (within warp): value at lane-1; A = q^lane implicit.
    float Ue = __shfl_up_sync(0xffffffffu, U, 1);
    float Ve = __shfl_up_sync(0xffffffffu, V, 1);

    if (lane == 31) sw[wid] = make_float2(U, V);
    __syncthreads();

    // Cross-warp scan over NWARPS=12 aggregates, redundant in every warp.
    // Step k factor = (q^32)^(2^k): keep squaring bA. Lanes >= NWARPS hold
    // junk that is never read (broadcast sources <= NWARPS-1).
    float cU = MAXOP ? -FLT_MAX : FLT_MAX, cV = 0.0f;
    if (lane < NWARPS) { float2 t = sw[lane]; cU = t.x; cV = t.y; }
    #pragma unroll
    for (int k = 0; k < 4; k++) {            // 12 warps -> 4 steps
        const int d = 1 << k;
        float uU = __shfl_up_sync(0xffffffffu, cU, d);
        float uV = __shfl_up_sync(0xffffffffu, cV, d);
        if (lane >= d) {
            cU = sel<MAXOP>(cU, fmaf(bA, uU, cV));
            cV = fmaf(bA, uV, cV);
        }
        bA *= bA;
    }

    // Warp-incoming resolved value: apply exclusive-over-warps to carry.
    const int src = (wid == 0) ? 0 : (wid - 1);
    float WU = __shfl_sync(0xffffffffu, cU, src);
    float WV = __shfl_sync(0xffffffffu, cV, src);
    float c_w = (wid == 0) ? carry : sel<MAXOP>(WU, fmaf(qwid, carry, WV));

    // Block total (lane NWARPS-1) for the carry update; factor qblk.
    float TU = __shfl_sync(0xffffffffu, cU, NWARPS - 1);
    float TV = __shfl_sync(0xffffffffu, cV, NWARPS - 1);
    float ncar = sel<MAXOP>(TU, fmaf(qblk, carry, TV));

    // Thread-incoming resolved value.
    float c = (lane == 0) ? c_w : sel<MAXOP>(Ue, fmaf(qlane, c_w, Ve));

    // Fixup: linear recurrence seeded with c; out = op(local, z).
    float z = c;
    #pragma unroll
    for (int j = 0; j < RPT; j++) {
        z = fmaf(alpha, z, om * in[j]);
        out[j] = sel<MAXOP>(out[j], z);
    }
    carry = ncar;
}

__global__ void __launch_bounds__(THREADS, 2)
tce_kernel(const float* __restrict__ x,
           const float* __restrict__ p_tauA,
           const float* __restrict__ p_tauD,
           const float* __restrict__ p_nu,
           const float* __restrict__ p_dbr,
           float* __restrict__ out, int T)
{
    __shared__ float2 swb[3][NWARPS];

    const int lane = threadIdx.x & 31;
    const int wid  = threadIdx.x >> 5;
    const long long ch = blockIdx.x;
    const float* xc = x + ch * (long long)T;
    float* oc = out + ch * (long long)T;

    // Scalar params (replicate reference clip chain)
    float tauA = fminf(fmaxf(p_tauA[0], 1.0f), 100.0f);
    tauA = fminf(fmaxf(tauA, 0.1f), 1000.0f) * 0.001f;
    const float aa = expf(-1.0f / (tauA * 44100.0f));
    float tauD = fminf(fmaxf(p_tauD[0], 1.0f), 100.0f);
    tauD = fminf(fmaxf(tauD, 0.1f), 1000.0f) * 0.001f;
    const float ad = expf(-1.0f / (tauD * 44100.0f));
    const float nuAmp = exp10f(fminf(fmaxf(p_nu[0], -60.0f), 0.0f) * 0.05f);
    const float reg   = exp10f(fminf(fmaxf(p_dbr[0], -120.0f), -60.0f) * 0.05f);
    const float omd = 1.0f - ad;
    const float oma = 1.0f - aa;

    // q = alpha^16 (4 squarings); qwarp = q^32; qblk = qwarp^12.
    float qd = ad * ad; qd *= qd; qd *= qd; qd *= qd;   // ad^16
    float qa = aa * aa; qa *= qa; qa *= qa; qa *= qa;   // aa^16
    float qwd = qd * qd; qwd *= qwd; qwd *= qwd;
    qwd *= qwd; qwd *= qwd;                             // qd^32
    float qwa = qa * qa; qwa *= qwa; qwa *= qwa;
    qwa *= qwa; qwa *= qwa;                             // qa^32
    // qwarp^12 = qwarp^8 * qwarp^4
    float w2d = qwd * qwd, w4d = w2d * w2d, w8d = w4d * w4d;
    float w2a = qwa * qwa, w4a = w2a * w2a, w8a = w4a * w4a;
    const float qblkd = w8d * w4d;
    const float qblka = w8a * w4a;

    // Per-lane q^lane; per-warp qwarp^wid (init-only loops).
    float qdlane = 1.0f, qalane = 1.0f;
    for (int i = 0; i < lane; i++) { qdlane *= qd; qalane *= qa; }
    float qwidd = 1.0f, qwida = 1.0f;
    for (int i = 0; i < wid; i++) { qwidd *= qwd; qwida *= qwa; }

    float cd = 0.0f, ca = 0.0f, ce = 0.0f;   // carries

    for (int base = 0; base < T; base += CHUNK) {
        const int off = base + (int)threadIdx.x * RPT;
        float A_[RPT], B_[RPT];

        // Load |x| (zero-padded beyond T; tail chunk only)
        #pragma unroll
        for (int g = 0; g < RPT / 4; g++) {
            const int o = off + g * 4;
            float4 v = make_float4(0.f, 0.f, 0.f, 0.f);
            if (o + 4 <= T) {
                v = *reinterpret_cast<const float4*>(xc + o);
            } else if (o < T) {
                v.x = xc[o];
                if (o + 1 < T) v.y = xc[o + 1];
                if (o + 2 < T) v.z = xc[o + 2];
            }
            A_[4 * g + 0] = fabsf(v.x);
            A_[4 * g + 1] = fabsf(v.y);
            A_[4 * g + 2] = fabsf(v.z);
            A_[4 * g + 3] = fabsf(v.w);
        }

        // et_d = envd(|x|)   (max, alpha_d):  A_ -> B_
        scan16<true >(A_, B_, ad, omd, qd, qdlane, qwidd, qblkd,
                      cd, swb[0], lane, wid);
        // et_a = enva(et_d)  (min, alpha_a):  B_ -> A_
        scan16<false>(B_, A_, aa, oma, qa, qalane, qwida, qblka,
                      ca, swb[1], lane, wid);
        // et = relu(et_d - et_a - nuAmp)   -> A_
        #pragma unroll
        for (int j = 0; j < RPT; j++)
            A_[j] = fmaxf(B_[j] - A_[j] - nuAmp, 0.0f);
        // et_env = envd(et)  (max, alpha_d):  A_ -> B_
        scan16<true >(A_, B_, ad, omd, qd, qdlane, qwidd, qblkd,
                      ce, swb[2], lane, wid);

        // out = x * et / (et_env + reg)   (x reloaded; L1/L2-hot)
        #pragma unroll
        for (int g = 0; g < RPT / 4; g++) {
            const int o = off + g * 4;
            if (o + 4 <= T) {
                float4 xv = *reinterpret_cast<const float4*>(xc + o);
                float4 r;
                r.x = xv.x * __fdividef(A_[4 * g + 0], B_[4 * g + 0] + reg);
                r.y = xv.y * __fdividef(A_[4 * g + 1], B_[4 * g + 1] + reg);
                r.z = xv.z * __fdividef(A_[4 * g + 2], B_[4 * g + 2] + reg);
                r.w = xv.w * __fdividef(A_[4 * g + 3], B_[4 * g + 3] + reg);
                *reinterpret_cast<float4*>(oc + o) = r;
            } else if (o < T) {
                oc[o] = xc[o] * __fdividef(A_[4 * g + 0], B_[4 * g + 0] + reg);
                if (o + 1 < T)
                    oc[o + 1] = xc[o + 1] * __fdividef(A_[4 * g + 1], B_[4 * g + 1] + reg);
                if (o + 2 < T)
                    oc[o + 2] = xc[o + 2] * __fdividef(A_[4 * g + 2], B_[4 * g + 2] + reg);
            }
        }
    }
}

extern "C" void kernel_launch(void* const* d_in, const int* in_sizes, int n_in,
                              void* d_out, int out_size)
{
    const float* x      = (const float*)d_in[0];
    const float* tauAtc = (const float*)d_in[1];
    const float* tauDtc = (const float*)d_in[2];
    const float* nu     = (const float*)d_in[3];
    const float* dbr    = (const float*)d_in[4];
    float* out = (float*)d_out;

    const int T = T_LEN;
    const int channels = in_sizes[0] / T;   // 256

    tce_kernel<<<channels, THREADS>>>(x, tauAtc, tauDtc, nu, dbr, out, T);
}